// round 1
// baseline (speedup 1.0000x reference)
#include <cuda_runtime.h>
#include <math_constants.h>

// Problem constants
#define Hh   16
#define Dd   64
#define Ee   1024
#define NBa  4
#define TBq  1024
#define TWq  512
#define NHh  64      // NBa*Hh
#define Rr   33      // 2L+1
#define Ll   16
#define SCALE 0.125f // D^-0.5

// ---------------- scratch (device globals; no allocation) ----------------
__device__ float g_q_bpe[NHh * TBq * Dd];
__device__ float g_k_bpe[NHh * TBq * Dd];
__device__ float g_v    [NHh * TBq * Dd];
__device__ float g_q_w  [NHh * TWq * Dd];
__device__ float g_k_w  [NHh * TWq * Dd];
__device__ float g_attn [NHh * TBq * TBq];   // 256 MB
__device__ float g_aw   [NHh * TWq * TWq];   // 64 MB
__device__ float g_tmp  [NHh * TBq * TWq];   // 128 MB
__device__ float g_arb  [NHh * TBq * Rr];
__device__ float g_arw  [NHh * TWq * Rr];
__device__ float g_x2   [TBq * NBa * Ee];

// ---------------- shared GEMM core ----------------
// Computes acc[TM][TN] += sum_k A[r,k] * opB, for the block tile whose
// (row0,col0) offsets have already been applied to A / Bq by the caller.
//   BT=true : Bq is [N,K] row-major (C = A * B^T), K-contiguous
//   BT=false: Bq is [K,N] row-major (C = A * B),  N-contiguous
// Requires (BM/TM)*(BN/TN)==256 threads, K % BK == 0, all dims % 4 == 0.
template<int BM, int BN, int BK, int TM, int TN, bool BT>
__device__ __forceinline__ void gemm_core(
    const float* __restrict__ A, const float* __restrict__ Bq,
    int K, int lda, int ldb, float acc[TM][TN])
{
    static_assert((BM / TM) * (BN / TN) == 256, "256 threads required");
    __shared__ __align__(16) float As[BK][BM];
    __shared__ __align__(16) float Bs[BK][BN];

    const int tid = threadIdx.x;
    const int tx  = tid % (BN / TN);
    const int ty  = tid / (BN / TN);

    for (int k0 = 0; k0 < K; k0 += BK) {
        // ---- stage A tile (transposed into As[k][m]) ----
        constexpr int AV = BM * BK / 4;
        #pragma unroll
        for (int v2 = tid; v2 < AV; v2 += 256) {
            int ar = v2 / (BK / 4);
            int ak = (v2 % (BK / 4)) * 4;
            float4 t = *(const float4*)(A + (size_t)ar * lda + k0 + ak);
            As[ak + 0][ar] = t.x; As[ak + 1][ar] = t.y;
            As[ak + 2][ar] = t.z; As[ak + 3][ar] = t.w;
        }
        // ---- stage B tile ----
        if (BT) {
            constexpr int BV = BN * BK / 4;
            #pragma unroll
            for (int v2 = tid; v2 < BV; v2 += 256) {
                int br = v2 / (BK / 4);
                int bk = (v2 % (BK / 4)) * 4;
                float4 t = *(const float4*)(Bq + (size_t)br * ldb + k0 + bk);
                Bs[bk + 0][br] = t.x; Bs[bk + 1][br] = t.y;
                Bs[bk + 2][br] = t.z; Bs[bk + 3][br] = t.w;
            }
        } else {
            constexpr int BV = BN * BK / 4;
            #pragma unroll
            for (int v2 = tid; v2 < BV; v2 += 256) {
                int bk = v2 / (BN / 4);
                int bn = (v2 % (BN / 4)) * 4;
                *(float4*)&Bs[bk][bn] =
                    *(const float4*)(Bq + (size_t)(k0 + bk) * ldb + bn);
            }
        }
        __syncthreads();

        #pragma unroll
        for (int kk = 0; kk < BK; kk++) {
            float a[TM], b[TN];
            #pragma unroll
            for (int i = 0; i < TM; i++) a[i] = As[kk][ty * TM + i];
            #pragma unroll
            for (int j = 0; j < TN; j++) b[j] = Bs[kk][tx * TN + j];
            #pragma unroll
            for (int i = 0; i < TM; i++)
                #pragma unroll
                for (int j = 0; j < TN; j++)
                    acc[i][j] += a[i] * b[j];
        }
        __syncthreads();
    }
}

// ---------------- stage kernels ----------------

// Projection: C[r,c] = (sum_k X[r,k]*W[c,k] + bias[c]) * scale,
// scattered to heads layout out[((bb*H+h)*T + t)*D + d], r = t*NB + bb, c = h*D + d.
__global__ void k_proj(const float* __restrict__ X, const float* __restrict__ W,
                       const float* __restrict__ bias, float* __restrict__ out,
                       int T, float scale)
{
    float acc[8][8] = {};
    int row0 = blockIdx.y * 128, col0 = blockIdx.x * 128;
    gemm_core<128, 128, 8, 8, 8, true>(X + (size_t)row0 * Ee, W + (size_t)col0 * Ee,
                                       Ee, Ee, Ee, acc);
    int tx = threadIdx.x % 16, ty = threadIdx.x / 16;
    #pragma unroll
    for (int i = 0; i < 8; i++) {
        int r = row0 + ty * 8 + i;
        int t = r / NBa, bb = r % NBa;
        #pragma unroll
        for (int j = 0; j < 8; j++) {
            int c = col0 + tx * 8 + j;
            int h = c / Dd, d = c % Dd;
            out[(((size_t)(bb * Hh + h)) * T + t) * Dd + d] =
                (acc[i][j] + bias[c]) * scale;
        }
    }
}

// Shaw relative table: allr[(n*T + t)*33 + r] = q[n,t,:] . table[r,:]
__global__ void k_allr(const float* __restrict__ q, const float* __restrict__ table,
                       float* __restrict__ allr, int T)
{
    int idx = blockIdx.x * blockDim.x + threadIdx.x;
    if (idx >= NHh * T * Rr) return;
    int r   = idx % Rr;
    int row = idx / Rr;
    const float* qp = q + (size_t)row * Dd;
    const float* tp = table + r * Dd;
    float s = 0.f;
    #pragma unroll
    for (int d = 0; d < Dd; d++) s += qp[d] * tp[d];
    allr[idx] = s;
}

// attn[z][t,s] = q[z,t,:] . k[z,s,:] + allr[z,t, clip(s-t,-L,L)+L]
__global__ void k_attn(const float* __restrict__ q, const float* __restrict__ k,
                       const float* __restrict__ allr, float* __restrict__ attn, int T)
{
    int z = blockIdx.z;
    const float* A  = q + (size_t)z * T * Dd;
    const float* Bp = k + (size_t)z * T * Dd;
    float acc[8][8] = {};
    int row0 = blockIdx.y * 128, col0 = blockIdx.x * 128;
    gemm_core<128, 128, 8, 8, 8, true>(A + (size_t)row0 * Dd, Bp + (size_t)col0 * Dd,
                                       Dd, Dd, Dd, acc);
    int tx = threadIdx.x % 16, ty = threadIdx.x / 16;
    #pragma unroll
    for (int i = 0; i < 8; i++) {
        int t = row0 + ty * 8 + i;
        const float* ar = allr + ((size_t)z * T + t) * Rr;
        #pragma unroll
        for (int j = 0; j < 8; j++) {
            int s = col0 + tx * 8 + j;
            int rel = s - t;
            rel = (rel < -Ll) ? -Ll : (rel > Ll ? Ll : rel);
            attn[((size_t)z * T + t) * T + s] = acc[i][j] + ar[rel + Ll];
        }
    }
}

// tmp[z][q,s'] = sum_w mapping[b][q,w] * aw[z][w,s']   (NN), b = z/H
__global__ void k_tmp(const float* __restrict__ mapping)
{
    int z = blockIdx.z, b = z / Hh;
    const float* A  = mapping + (size_t)b * TBq * TWq;
    const float* Bp = g_aw    + (size_t)z * TWq * TWq;
    float acc[8][8] = {};
    int row0 = blockIdx.y * 128, col0 = blockIdx.x * 128;
    gemm_core<128, 128, 8, 8, 8, false>(A + (size_t)row0 * TWq, Bp + col0,
                                        TWq, TWq, TWq, acc);
    int tx = threadIdx.x % 16, ty = threadIdx.x / 16;
    #pragma unroll
    for (int i = 0; i < 8; i++)
        #pragma unroll
        for (int j = 0; j < 8; j++)
            g_tmp[((size_t)z * TBq + row0 + ty * 8 + i) * TWq + col0 + tx * 8 + j]
                = acc[i][j];
}

// attn[z][q,s] += sum_s' tmp[z][q,s'] * mapping[b][s,s']   (NT)
__global__ void k_fuse(const float* __restrict__ mapping)
{
    int z = blockIdx.z, b = z / Hh;
    const float* A  = g_tmp   + (size_t)z * TBq * TWq;
    const float* Bp = mapping + (size_t)b * TBq * TWq;
    float acc[8][8] = {};
    int row0 = blockIdx.y * 128, col0 = blockIdx.x * 128;
    gemm_core<128, 128, 8, 8, 8, true>(A + (size_t)row0 * TWq, Bp + (size_t)col0 * TWq,
                                       TWq, TWq, TWq, acc);
    int tx = threadIdx.x % 16, ty = threadIdx.x / 16;
    #pragma unroll
    for (int i = 0; i < 8; i++)
        #pragma unroll
        for (int j = 0; j < 8; j++) {
            size_t o = ((size_t)z * TBq + row0 + ty * 8 + i) * TBq + col0 + tx * 8 + j;
            g_attn[o] += acc[i][j];
        }
}

// row-wise softmax over last dim (in place), row length TBq, 256 threads/block
__global__ void k_softmax()
{
    const size_t row = blockIdx.x;
    float4* p = (float4*)(g_attn + row * TBq);
    float4 v = p[threadIdx.x];
    float m = fmaxf(fmaxf(v.x, v.y), fmaxf(v.z, v.w));

    __shared__ float smx[8];
    __shared__ float ssm[8];
    int lane = threadIdx.x & 31, w = threadIdx.x >> 5;
    #pragma unroll
    for (int o = 16; o; o >>= 1) m = fmaxf(m, __shfl_xor_sync(0xffffffffu, m, o));
    if (!lane) smx[w] = m;
    __syncthreads();
    m = smx[0];
    #pragma unroll
    for (int i = 1; i < 8; i++) m = fmaxf(m, smx[i]);

    v.x = expf(v.x - m); v.y = expf(v.y - m);
    v.z = expf(v.z - m); v.w = expf(v.w - m);
    float s = v.x + v.y + v.z + v.w;
    #pragma unroll
    for (int o = 16; o; o >>= 1) s += __shfl_xor_sync(0xffffffffu, s, o);
    if (!lane) ssm[w] = s;
    __syncthreads();
    s = 0.f;
    #pragma unroll
    for (int i = 0; i < 8; i++) s += ssm[i];

    float inv = 1.f / s;
    v.x *= inv; v.y *= inv; v.z *= inv; v.w *= inv;
    p[threadIdx.x] = v;
}

// x2[(t*NB+bb)*E + h*D + d] = sum_s probs[z][t,s] * v[z][s,d]   (NN, N=64)
__global__ void k_pv()
{
    int z = blockIdx.z, bb = z / Hh, h = z % Hh;
    const float* A  = g_attn + (size_t)z * TBq * TBq;
    const float* Bp = g_v    + (size_t)z * TBq * Dd;
    float acc[8][4] = {};
    int row0 = blockIdx.y * 128, col0 = blockIdx.x * 64;
    gemm_core<128, 64, 8, 8, 4, false>(A + (size_t)row0 * TBq, Bp + col0,
                                       TBq, TBq, Dd, acc);
    int tx = threadIdx.x % 16, ty = threadIdx.x / 16;
    #pragma unroll
    for (int i = 0; i < 8; i++) {
        int t = row0 + ty * 8 + i;
        #pragma unroll
        for (int j = 0; j < 4; j++) {
            int d = col0 + tx * 4 + j;
            g_x2[((size_t)t * NBa + bb) * Ee + h * Dd + d] = acc[i][j];
        }
    }
}

// out[r,c] = sum_k x2[r,k] * Wo[c,k] + bo[c]
__global__ void k_final(const float* __restrict__ Wo, const float* __restrict__ bo,
                        float* __restrict__ out)
{
    float acc[8][8] = {};
    int row0 = blockIdx.y * 128, col0 = blockIdx.x * 128;
    gemm_core<128, 128, 8, 8, 8, true>(g_x2 + (size_t)row0 * Ee, Wo + (size_t)col0 * Ee,
                                       Ee, Ee, Ee, acc);
    int tx = threadIdx.x % 16, ty = threadIdx.x / 16;
    #pragma unroll
    for (int i = 0; i < 8; i++)
        #pragma unroll
        for (int j = 0; j < 8; j++) {
            int r = row0 + ty * 8 + i, c = col0 + tx * 8 + j;
            out[(size_t)r * Ee + c] = acc[i][j] + bo[c];
        }
}

// ---------------- launcher ----------------
extern "C" void kernel_launch(void* const* d_in, const int* in_sizes, int n_in,
                              void* d_out, int out_size)
{
    const float* query_bpe  = (const float*)d_in[0];
    const float* query_word = (const float*)d_in[1];
    const float* mapping    = (const float*)d_in[2];
    const float* Wq_bpe     = (const float*)d_in[3];
    const float* bq_bpe     = (const float*)d_in[4];
    const float* Wk_bpe     = (const float*)d_in[5];
    const float* bk_bpe     = (const float*)d_in[6];
    const float* Wq_word    = (const float*)d_in[7];
    const float* bq_word    = (const float*)d_in[8];
    const float* Wk_word    = (const float*)d_in[9];
    const float* bk_word    = (const float*)d_in[10];
    const float* Wv         = (const float*)d_in[11];
    const float* bv         = (const float*)d_in[12];
    const float* Wo         = (const float*)d_in[13];
    const float* bo         = (const float*)d_in[14];
    const float* rel_keys   = (const float*)d_in[15];
    float* out = (float*)d_out;

    float *q_bpe, *k_bpe, *v, *q_w, *k_w, *attn, *aw, *arb, *arw;
    cudaGetSymbolAddress((void**)&q_bpe, g_q_bpe);
    cudaGetSymbolAddress((void**)&k_bpe, g_k_bpe);
    cudaGetSymbolAddress((void**)&v,     g_v);
    cudaGetSymbolAddress((void**)&q_w,   g_q_w);
    cudaGetSymbolAddress((void**)&k_w,   g_k_w);
    cudaGetSymbolAddress((void**)&attn,  g_attn);
    cudaGetSymbolAddress((void**)&aw,    g_aw);
    cudaGetSymbolAddress((void**)&arb,   g_arb);
    cudaGetSymbolAddress((void**)&arw,   g_arw);

    // projections  (M = T*NB rows)
    k_proj<<<dim3(8, 32), 256>>>(query_bpe,  Wq_bpe,  bq_bpe,  q_bpe, TBq, SCALE);
    k_proj<<<dim3(8, 32), 256>>>(query_bpe,  Wk_bpe,  bk_bpe,  k_bpe, TBq, 1.0f);
    k_proj<<<dim3(8, 32), 256>>>(query_bpe,  Wv,      bv,      v,     TBq, 1.0f);
    k_proj<<<dim3(8, 16), 256>>>(query_word, Wq_word, bq_word, q_w,   TWq, SCALE);
    k_proj<<<dim3(8, 16), 256>>>(query_word, Wk_word, bk_word, k_w,   TWq, 1.0f);

    // relative logit tables
    k_allr<<<(NHh * TBq * Rr + 255) / 256, 256>>>(q_bpe, rel_keys, arb, TBq);
    k_allr<<<(NHh * TWq * Rr + 255) / 256, 256>>>(q_w,   rel_keys, arw, TWq);

    // content + relative logits
    k_attn<<<dim3(8, 8, NHh), 256>>>(q_bpe, k_bpe, arb, attn, TBq);
    k_attn<<<dim3(4, 4, NHh), 256>>>(q_w,   k_w,   arw, aw,   TWq);

    // fusion: tmp = M @ aw ; attn += tmp @ M^T
    k_tmp <<<dim3(4, 8, NHh), 256>>>(mapping);
    k_fuse<<<dim3(8, 8, NHh), 256>>>(mapping);

    // softmax rows
    k_softmax<<<NHh * TBq, 256>>>();

    // probs @ v -> x2 (head regather)
    k_pv<<<dim3(1, 8, NHh), 256>>>();

    // output projection
    k_final<<<dim3(8, 32), 256>>>(Wo, bo, out);
}

// round 3
// speedup vs baseline: 1.3384x; 1.3384x over previous
#include <cuda_runtime.h>
#include <cstdint>

// Problem constants
#define Hh   16
#define Dd   64
#define Ee   1024
#define NBa  4
#define TBq  1024
#define TWq  512
#define NHh  64      // NBa*Hh
#define Rr   33      // 2L+1
#define Ll   16
#define SCALE 0.125f // D^-0.5

// ---------------- scratch (device globals; no allocation) ----------------
__device__ float g_q_bpe[NHh * TBq * Dd];
__device__ float g_k_bpe[NHh * TBq * Dd];
__device__ float g_v    [NHh * TBq * Dd];
__device__ float g_q_w  [NHh * TWq * Dd];
__device__ float g_k_w  [NHh * TWq * Dd];
__device__ float g_attn [NHh * TBq * TBq];   // 256 MB
__device__ float g_awT  [NHh * TWq * TWq];   // 64 MB (word logits transposed [s',w])
__device__ float g_tmp  [NHh * TBq * TWq];   // 128 MB
__device__ float g_arb  [NHh * TBq * Rr];
__device__ float g_arw  [NHh * TWq * Rr];
__device__ float g_x2   [TBq * NBa * Ee];

// ================== portable tf32 mma.sync GEMM core ==================
// C = A * B^T. A:[M,K] row-major(lda), B:[N,K] row-major(ldb), fp32 gmem.
// 3xTF32 split for ~fp32 accuracy. Tile 128x128, BK=16, 256 threads.
// SMEM per stage (floats): AH[128][20] AL BH BL = 10240; double buffered.
#define SA    20
#define SBUF  10240
#define MM_SMEM (2 * SBUF * 4)

__device__ __forceinline__ void ptx_mma(float* c, const uint32_t* a, const uint32_t* b) {
    asm volatile(
        "mma.sync.aligned.m16n8k8.row.col.f32.tf32.tf32.f32 "
        "{%0,%1,%2,%3},{%4,%5,%6,%7},{%8,%9},{%0,%1,%2,%3};"
        : "+f"(c[0]), "+f"(c[1]), "+f"(c[2]), "+f"(c[3])
        : "r"(a[0]), "r"(a[1]), "r"(a[2]), "r"(a[3]), "r"(b[0]), "r"(b[1]));
}

__device__ __forceinline__ void split_store(float* base, int r, int kq, float4 v) {
    float* hp = base + r * SA + kq;
    float* lp = hp + 2560;
    float xs[4] = {v.x, v.y, v.z, v.w};
    #pragma unroll
    for (int i = 0; i < 4; i++) {
        uint32_t hb;
        asm("cvt.rna.tf32.f32 %0,%1;" : "=r"(hb) : "f"(xs[i]));
        float hf = __uint_as_float(hb);
        float lf = xs[i] - hf;
        uint32_t lb;
        asm("cvt.rna.tf32.f32 %0,%1;" : "=r"(lb) : "f"(lf));
        hp[i] = hf;
        lp[i] = __uint_as_float(lb);
    }
}

__device__ __forceinline__ void mm_core_tf32(
    const float* __restrict__ A, const float* __restrict__ B,
    int lda, int ldb, int K, float acc[4][4][4], float* sm)
{
    const int tid = threadIdx.x, lane = tid & 31, wid = tid >> 5;
    const int wm = wid >> 2, wn = wid & 3, lr = lane >> 2, lc = lane & 3;
    const int fr = tid >> 2, fk = (tid & 3) << 2;

    float4 fa0, fa1, fb0, fb1;
    fa0 = *(const float4*)(A + (size_t)fr * lda + fk);
    fa1 = *(const float4*)(A + (size_t)(fr + 64) * lda + fk);
    fb0 = *(const float4*)(B + (size_t)fr * ldb + fk);
    fb1 = *(const float4*)(B + (size_t)(fr + 64) * ldb + fk);
    split_store(sm,        fr,      fk, fa0);
    split_store(sm,        fr + 64, fk, fa1);
    split_store(sm + 5120, fr,      fk, fb0);
    split_store(sm + 5120, fr + 64, fk, fb1);
    __syncthreads();

    const int NIT = K >> 4;
    for (int it = 0; it < NIT; it++) {
        if (it + 1 < NIT) {
            const int k0 = (it + 1) << 4;
            fa0 = *(const float4*)(A + (size_t)fr * lda + k0 + fk);
            fa1 = *(const float4*)(A + (size_t)(fr + 64) * lda + k0 + fk);
            fb0 = *(const float4*)(B + (size_t)fr * ldb + k0 + fk);
            fb1 = *(const float4*)(B + (size_t)(fr + 64) * ldb + k0 + fk);
        }
        const float* s  = sm + (it & 1) * SBUF;
        const float* AH = s;
        const float* AL = s + 2560;
        const float* BH = s + 5120;
        const float* BL = s + 7680;
        #pragma unroll
        for (int ks = 0; ks < 2; ks++) {
            const int k0 = ks * 8 + lc;
            uint32_t ah[4][4], al[4][4], bh[4][2], bl[4][2];
            #pragma unroll
            for (int mf = 0; mf < 4; mf++) {
                const int rb = wm * 64 + mf * 16 + lr;
                const float* p0 = AH + rb * SA + k0;
                const float* p1 = AH + (rb + 8) * SA + k0;
                ah[mf][0] = __float_as_uint(p0[0]);
                ah[mf][1] = __float_as_uint(p1[0]);
                ah[mf][2] = __float_as_uint(p0[4]);
                ah[mf][3] = __float_as_uint(p1[4]);
                const float* q0 = AL + rb * SA + k0;
                const float* q1 = AL + (rb + 8) * SA + k0;
                al[mf][0] = __float_as_uint(q0[0]);
                al[mf][1] = __float_as_uint(q1[0]);
                al[mf][2] = __float_as_uint(q0[4]);
                al[mf][3] = __float_as_uint(q1[4]);
            }
            #pragma unroll
            for (int nf = 0; nf < 4; nf++) {
                const int nb = wn * 32 + nf * 8 + lr;
                const float* p = BH + nb * SA + k0;
                bh[nf][0] = __float_as_uint(p[0]);
                bh[nf][1] = __float_as_uint(p[4]);
                const float* q = BL + nb * SA + k0;
                bl[nf][0] = __float_as_uint(q[0]);
                bl[nf][1] = __float_as_uint(q[4]);
            }
            #pragma unroll
            for (int mf = 0; mf < 4; mf++)
                #pragma unroll
                for (int nf = 0; nf < 4; nf++) {
                    ptx_mma(acc[mf][nf], ah[mf], bh[nf]);
                    ptx_mma(acc[mf][nf], ah[mf], bl[nf]);
                    ptx_mma(acc[mf][nf], al[mf], bh[nf]);
                }
        }
        if (it + 1 < NIT) {
            float* d = sm + ((it + 1) & 1) * SBUF;
            split_store(d,        fr,      fk, fa0);
            split_store(d,        fr + 64, fk, fa1);
            split_store(d + 5120, fr,      fk, fb0);
            split_store(d + 5120, fr + 64, fk, fb1);
            __syncthreads();
        }
    }
}

// epilogue iteration helper: yields (r,cI,v0,v1) local coords within 128x128 tile
#define EPI_BEGIN \
    const int lane_ = threadIdx.x & 31, wid_ = threadIdx.x >> 5; \
    const int wm_ = wid_ >> 2, wn_ = wid_ & 3, lr_ = lane_ >> 2, lc_ = lane_ & 3; \
    _Pragma("unroll") for (int mf = 0; mf < 4; mf++) \
    _Pragma("unroll") for (int nf = 0; nf < 4; nf++) \
    _Pragma("unroll") for (int hf = 0; hf < 2; hf++) { \
        const int r  = wm_ * 64 + mf * 16 + lr_ + hf * 8; \
        const int cI = wn_ * 32 + nf * 8 + lc_ * 2; \
        const float v0 = acc[mf][nf][hf * 2], v1 = acc[mf][nf][hf * 2 + 1];
#define EPI_END }

// ---------------- mma-based kernels ----------------

// projection + bias + scale + head scatter
__global__ void __launch_bounds__(256, 1) k_proj_mma(
    const float* __restrict__ X, const float* __restrict__ W,
    const float* __restrict__ bias, float* __restrict__ out, int T, float scale)
{
    extern __shared__ float sm[];
    float acc[4][4][4] = {};
    const int row0 = blockIdx.y * 128, col0 = blockIdx.x * 128;
    mm_core_tf32(X + (size_t)row0 * Ee, W + (size_t)col0 * Ee, Ee, Ee, Ee, acc, sm);
    EPI_BEGIN
        const int gr = row0 + r, gc = col0 + cI;
        const int t = gr >> 2, bb = gr & 3;
        const int h = gc >> 6, d = gc & 63;
        float2 v = make_float2((v0 + bias[gc]) * scale, (v1 + bias[gc + 1]) * scale);
        *(float2*)&out[(((size_t)(bb * Hh + h)) * T + t) * Dd + d] = v;
    EPI_END
}

// QK^T + relative logits; transp selects transposed store (for word stream)
__global__ void __launch_bounds__(256, 1) k_attn_mma(
    const float* __restrict__ q, const float* __restrict__ k,
    const float* __restrict__ allr, float* __restrict__ attn, int T, int transp)
{
    extern __shared__ float sm[];
    const int z = blockIdx.z;
    const int row0 = blockIdx.y * 128, col0 = blockIdx.x * 128;
    const float* A = q + (size_t)z * T * Dd + (size_t)row0 * Dd;
    const float* B = k + (size_t)z * T * Dd + (size_t)col0 * Dd;
    float acc[4][4][4] = {};
    mm_core_tf32(A, B, Dd, Dd, Dd, acc, sm);
    EPI_BEGIN
        const int t = row0 + r;
        const int s0 = col0 + cI;
        const float* ar = allr + ((size_t)z * T + t) * Rr;
        int r0c = s0 - t;     r0c = r0c < -Ll ? -Ll : (r0c > Ll ? Ll : r0c);
        int r1c = s0 + 1 - t; r1c = r1c < -Ll ? -Ll : (r1c > Ll ? Ll : r1c);
        const float o0 = v0 + ar[r0c + Ll];
        const float o1 = v1 + ar[r1c + Ll];
        if (transp) {
            attn[((size_t)z * T + s0) * T + t]     = o0;
            attn[((size_t)z * T + s0 + 1) * T + t] = o1;
        } else {
            *(float2*)&attn[((size_t)z * T + t) * T + s0] = make_float2(o0, o1);
        }
    EPI_END
}

// batched NT GEMM: C[z] (+)= A[z/aZd] * B[z/bZd]^T
template<bool ADD>
__global__ void __launch_bounds__(256, 1) k_mmNT(
    const float* __restrict__ Ab, const float* __restrict__ Bb, float* __restrict__ Cb,
    int lda, int ldb, int ldc, int K,
    long long aZs, int aZd, long long bZs, int bZd, long long cZs)
{
    extern __shared__ float sm[];
    const int z = blockIdx.z;
    const int row0 = blockIdx.y * 128, col0 = blockIdx.x * 128;
    const float* A = Ab + (size_t)(z / aZd) * aZs + (size_t)row0 * lda;
    const float* B = Bb + (size_t)(z / bZd) * bZs + (size_t)col0 * ldb;
    float* C = Cb + (size_t)z * cZs;
    float acc[4][4][4] = {};
    mm_core_tf32(A, B, lda, ldb, K, acc, sm);
    EPI_BEGIN
        float2* p = (float2*)&C[(size_t)(row0 + r) * ldc + col0 + cI];
        float2 v = make_float2(v0, v1);
        if (ADD) { float2 o = *p; v.x += o.x; v.y += o.y; }
        *p = v;
    EPI_END
}

// output projection + bias
__global__ void __launch_bounds__(256, 1) k_final_mma(
    const float* __restrict__ X, const float* __restrict__ Wo,
    const float* __restrict__ bo, float* __restrict__ out)
{
    extern __shared__ float sm[];
    float acc[4][4][4] = {};
    const int row0 = blockIdx.y * 128, col0 = blockIdx.x * 128;
    mm_core_tf32(X + (size_t)row0 * Ee, Wo + (size_t)col0 * Ee, Ee, Ee, Ee, acc, sm);
    EPI_BEGIN
        const int gr = row0 + r, gc = col0 + cI;
        *(float2*)&out[(size_t)gr * Ee + gc] = make_float2(v0 + bo[gc], v1 + bo[gc + 1]);
    EPI_END
}

// ---------------- SIMT GEMM core (for k_pv) ----------------
template<int BM, int BN, int BK, int TM, int TN, bool BT>
__device__ __forceinline__ void gemm_core(
    const float* __restrict__ A, const float* __restrict__ Bq,
    int K, int lda, int ldb, float acc[TM][TN])
{
    __shared__ __align__(16) float As[BK][BM];
    __shared__ __align__(16) float Bs[BK][BN];
    const int tid = threadIdx.x;
    const int tx  = tid % (BN / TN);
    const int ty  = tid / (BN / TN);

    for (int k0 = 0; k0 < K; k0 += BK) {
        constexpr int AV = BM * BK / 4;
        #pragma unroll
        for (int v2 = tid; v2 < AV; v2 += 256) {
            int ar = v2 / (BK / 4);
            int ak = (v2 % (BK / 4)) * 4;
            float4 t = *(const float4*)(A + (size_t)ar * lda + k0 + ak);
            As[ak + 0][ar] = t.x; As[ak + 1][ar] = t.y;
            As[ak + 2][ar] = t.z; As[ak + 3][ar] = t.w;
        }
        constexpr int BV = BN * BK / 4;
        #pragma unroll
        for (int v2 = tid; v2 < BV; v2 += 256) {
            if (BT) {
                int br = v2 / (BK / 4);
                int bk = (v2 % (BK / 4)) * 4;
                float4 t = *(const float4*)(Bq + (size_t)br * ldb + k0 + bk);
                Bs[bk + 0][br] = t.x; Bs[bk + 1][br] = t.y;
                Bs[bk + 2][br] = t.z; Bs[bk + 3][br] = t.w;
            } else {
                int bk = v2 / (BN / 4);
                int bn = (v2 % (BN / 4)) * 4;
                *(float4*)&Bs[bk][bn] =
                    *(const float4*)(Bq + (size_t)(k0 + bk) * ldb + bn);
            }
        }
        __syncthreads();
        #pragma unroll
        for (int kk = 0; kk < BK; kk++) {
            float a[TM], b[TN];
            #pragma unroll
            for (int i = 0; i < TM; i++) a[i] = As[kk][ty * TM + i];
            #pragma unroll
            for (int j = 0; j < TN; j++) b[j] = Bs[kk][tx * TN + j];
            #pragma unroll
            for (int i = 0; i < TM; i++)
                #pragma unroll
                for (int j = 0; j < TN; j++)
                    acc[i][j] += a[i] * b[j];
        }
        __syncthreads();
    }
}

// ---------------- remaining SIMT kernels ----------------
__global__ void k_allr(const float* __restrict__ q, const float* __restrict__ table,
                       float* __restrict__ allr, int T)
{
    int idx = blockIdx.x * blockDim.x + threadIdx.x;
    if (idx >= NHh * T * Rr) return;
    int r   = idx % Rr;
    int row = idx / Rr;
    const float* qp = q + (size_t)row * Dd;
    const float* tp = table + r * Dd;
    float s = 0.f;
    #pragma unroll
    for (int d = 0; d < Dd; d++) s += qp[d] * tp[d];
    allr[idx] = s;
}

__global__ void k_softmax()
{
    const size_t row = blockIdx.x;
    float4* p = (float4*)(g_attn + row * TBq);
    float4 v = p[threadIdx.x];
    float m = fmaxf(fmaxf(v.x, v.y), fmaxf(v.z, v.w));

    __shared__ float smx[8];
    __shared__ float ssm[8];
    int lane = threadIdx.x & 31, w = threadIdx.x >> 5;
    #pragma unroll
    for (int o = 16; o; o >>= 1) m = fmaxf(m, __shfl_xor_sync(0xffffffffu, m, o));
    if (!lane) smx[w] = m;
    __syncthreads();
    m = smx[0];
    #pragma unroll
    for (int i = 1; i < 8; i++) m = fmaxf(m, smx[i]);

    v.x = expf(v.x - m); v.y = expf(v.y - m);
    v.z = expf(v.z - m); v.w = expf(v.w - m);
    float s = v.x + v.y + v.z + v.w;
    #pragma unroll
    for (int o = 16; o; o >>= 1) s += __shfl_xor_sync(0xffffffffu, s, o);
    if (!lane) ssm[w] = s;
    __syncthreads();
    s = 0.f;
    #pragma unroll
    for (int i = 0; i < 8; i++) s += ssm[i];

    float inv = 1.f / s;
    v.x *= inv; v.y *= inv; v.z *= inv; v.w *= inv;
    p[threadIdx.x] = v;
}

__global__ void k_pv()
{
    int z = blockIdx.z, bb = z / Hh, h = z % Hh;
    const float* A  = g_attn + (size_t)z * TBq * TBq;
    const float* Bp = g_v    + (size_t)z * TBq * Dd;
    float acc[8][4] = {};
    int row0 = blockIdx.y * 128, col0 = blockIdx.x * 64;
    gemm_core<128, 64, 8, 8, 4, false>(A + (size_t)row0 * TBq, Bp + col0,
                                       TBq, TBq, Dd, acc);
    int tx = threadIdx.x % 16, ty = threadIdx.x / 16;
    #pragma unroll
    for (int i = 0; i < 8; i++) {
        int t = row0 + ty * 8 + i;
        #pragma unroll
        for (int j = 0; j < 4; j++) {
            int d = col0 + tx * 4 + j;
            g_x2[((size_t)t * NBa + bb) * Ee + h * Dd + d] = acc[i][j];
        }
    }
}

// ---------------- launcher ----------------
extern "C" void kernel_launch(void* const* d_in, const int* in_sizes, int n_in,
                              void* d_out, int out_size)
{
    const float* query_bpe  = (const float*)d_in[0];
    const float* query_word = (const float*)d_in[1];
    const float* mapping    = (const float*)d_in[2];
    const float* Wq_bpe     = (const float*)d_in[3];
    const float* bq_bpe     = (const float*)d_in[4];
    const float* Wk_bpe     = (const float*)d_in[5];
    const float* bk_bpe     = (const float*)d_in[6];
    const float* Wq_word    = (const float*)d_in[7];
    const float* bq_word    = (const float*)d_in[8];
    const float* Wk_word    = (const float*)d_in[9];
    const float* bk_word    = (const float*)d_in[10];
    const float* Wv         = (const float*)d_in[11];
    const float* bv         = (const float*)d_in[12];
    const float* Wo         = (const float*)d_in[13];
    const float* bo         = (const float*)d_in[14];
    const float* rel_keys   = (const float*)d_in[15];
    float* out = (float*)d_out;

    float *q_bpe, *k_bpe, *v, *q_w, *k_w, *attn, *awT, *tmp, *arb, *arw, *x2;
    cudaGetSymbolAddress((void**)&q_bpe, g_q_bpe);
    cudaGetSymbolAddress((void**)&k_bpe, g_k_bpe);
    cudaGetSymbolAddress((void**)&v,     g_v);
    cudaGetSymbolAddress((void**)&q_w,   g_q_w);
    cudaGetSymbolAddress((void**)&k_w,   g_k_w);
    cudaGetSymbolAddress((void**)&attn,  g_attn);
    cudaGetSymbolAddress((void**)&awT,   g_awT);
    cudaGetSymbolAddress((void**)&tmp,   g_tmp);
    cudaGetSymbolAddress((void**)&arb,   g_arb);
    cudaGetSymbolAddress((void**)&arw,   g_arw);
    cudaGetSymbolAddress((void**)&x2,    g_x2);

    cudaFuncSetAttribute(k_proj_mma,  cudaFuncAttributeMaxDynamicSharedMemorySize, MM_SMEM);
    cudaFuncSetAttribute(k_attn_mma,  cudaFuncAttributeMaxDynamicSharedMemorySize, MM_SMEM);
    cudaFuncSetAttribute(k_mmNT<false>, cudaFuncAttributeMaxDynamicSharedMemorySize, MM_SMEM);
    cudaFuncSetAttribute(k_mmNT<true>,  cudaFuncAttributeMaxDynamicSharedMemorySize, MM_SMEM);
    cudaFuncSetAttribute(k_final_mma, cudaFuncAttributeMaxDynamicSharedMemorySize, MM_SMEM);

    // projections (M = T*NB rows)
    k_proj_mma<<<dim3(8, 32), 256, MM_SMEM>>>(query_bpe,  Wq_bpe,  bq_bpe,  q_bpe, TBq, SCALE);
    k_proj_mma<<<dim3(8, 32), 256, MM_SMEM>>>(query_bpe,  Wk_bpe,  bk_bpe,  k_bpe, TBq, 1.0f);
    k_proj_mma<<<dim3(8, 32), 256, MM_SMEM>>>(query_bpe,  Wv,      bv,      v,     TBq, 1.0f);
    k_proj_mma<<<dim3(8, 16), 256, MM_SMEM>>>(query_word, Wq_word, bq_word, q_w,   TWq, SCALE);
    k_proj_mma<<<dim3(8, 16), 256, MM_SMEM>>>(query_word, Wk_word, bk_word, k_w,   TWq, 1.0f);

    // relative logit tables
    k_allr<<<(NHh * TBq * Rr + 255) / 256, 256>>>(q_bpe, rel_keys, arb, TBq);
    k_allr<<<(NHh * TWq * Rr + 255) / 256, 256>>>(q_w,   rel_keys, arw, TWq);

    // content + relative logits; word stream written TRANSPOSED (awT[s',w])
    k_attn_mma<<<dim3(8, 8, NHh), 256, MM_SMEM>>>(q_bpe, k_bpe, arb, attn, TBq, 0);
    k_attn_mma<<<dim3(4, 4, NHh), 256, MM_SMEM>>>(q_w,   k_w,   arw, awT,  TWq, 1);

    // fusion chain on tensor cores:
    // tmp[z] = mapping[b] @ awT[z]^T
    k_mmNT<false><<<dim3(TWq / 128, TBq / 128, NHh), 256, MM_SMEM>>>(
        mapping, awT, tmp, TWq, TWq, TWq, TWq,
        (long long)TBq * TWq, Hh, (long long)TWq * TWq, 1, (long long)TBq * TWq);
    // attn[z] += tmp[z] @ mapping[b]^T
    k_mmNT<true><<<dim3(TBq / 128, TBq / 128, NHh), 256, MM_SMEM>>>(
        tmp, mapping, attn, TWq, TWq, TBq, TWq,
        (long long)TBq * TWq, 1, (long long)TBq * TWq, Hh, (long long)TBq * TBq);

    // softmax rows
    k_softmax<<<NHh * TBq, 256>>>();

    // probs @ v -> x2 (head regather)
    k_pv<<<dim3(1, 8, NHh), 256>>>();

    // output projection
    k_final_mma<<<dim3(8, 32), 256, MM_SMEM>>>(x2, Wo, bo, out);
}